// round 10
// baseline (speedup 1.0000x reference)
#include <cuda_runtime.h>
#include <math.h>

// Problem constants
#define BB 2
#define NN 512
#define CC 151
#define DD 4096
#define SCORE_THRESH 0.05f
#define NMS_THRESH_F 0.5f
#define TOPN_PER_CLS 300
#define DET_PER_IMG 100
#define W_CLIP 799.0f
#define H_CLIP 599.0f

#define GRID 148
#define TPB  1024

// input element counts (for pointer identification)
#define SZ_LOGITS (BB*NN*CC)       // 154624
#define SZ_REG    (BB*NN*CC*4)     // 618496
#define SZ_PROPS  (BB*NN*4)        // 4096
#define SZ_FEATS  (BB*NN*DD)       // 4194304

// output layout (float32)
#define OFF_BOXES  0
#define OFF_SCORES (BB*NN*4)            // 4096
#define OFF_LABELS (OFF_SCORES + BB*NN) // 5120
#define OFF_VALID  (OFF_LABELS + BB*NN) // 6144
#define OFF_FEATS  (OFF_VALID + BB*NN)  // 7168

// scratch (device globals; no allocation allowed)
__device__ float g_prob[BB*CC*NN];                 // [b][c][n]
__device__ unsigned long long g_best[BB*NN];       // packed (score_bits<<32)|(CC-label)
__device__ float g_validf[BB*NN];                  // 1.0/0.0 mask for features

// grid barrier state (monotone generation; survives graph replays)
__device__ unsigned g_count = 0;
__device__ unsigned g_gen   = 0;

__device__ __forceinline__ void grid_sync()
{
    __syncthreads();
    if (threadIdx.x == 0) {
        __threadfence();
        unsigned gen = *(volatile unsigned*)&g_gen;
        if (atomicAdd(&g_count, 1u) == GRID - 1u) {
            atomicExch(&g_count, 0u);
            __threadfence();
            atomicAdd(&g_gen, 1u);
        } else {
            while (*(volatile unsigned*)&g_gen == gen) { __nanosleep(32); }
        }
        __threadfence();
    }
    __syncthreads();
}

// ---------------------------------------------------------------------------
// decode stays double (few K calls; feeds output boxes + IoU inputs)
// ---------------------------------------------------------------------------
__device__ __forceinline__ void decode_clip(const float* pb, const float* rg,
                                            float& X1, float& Y1, float& X2, float& Y2)
{
    const double DCLAMP = (double)(float)log(62.5);  // float(np.log(1000/16))
    double x1 = pb[0], y1 = pb[1], x2 = pb[2], y2 = pb[3];
    double w = x2 - x1 + 1.0, h = y2 - y1 + 1.0;
    double cx = x1 + 0.5 * w, cy = y1 + 0.5 * h;
    double dx = (double)rg[0] / 10.0;
    double dy = (double)rg[1] / 10.0;
    double dw = fmin((double)rg[2] / 5.0, DCLAMP);
    double dh = fmin((double)rg[3] / 5.0, DCLAMP);
    double pcx = dx * w + cx, pcy = dy * h + cy;
    double pw = exp(dw) * w, ph = exp(dh) * h;
    float a = (float)(pcx - 0.5 * pw);
    float b = (float)(pcy - 0.5 * ph);
    float c = (float)(pcx + 0.5 * pw - 1.0);
    float d = (float)(pcy + 0.5 * ph - 1.0);
    X1 = fminf(fmaxf(a, 0.f), W_CLIP);
    Y1 = fminf(fmaxf(b, 0.f), H_CLIP);
    X2 = fminf(fmaxf(c, 0.f), W_CLIP);
    Y2 = fminf(fmaxf(d, 0.f), H_CLIP);
}

// float IoU, exact reference formula order (Pascal +1 convention)
__device__ __forceinline__ float iou_f(float ax1, float ay1, float ax2, float ay2, float areaA,
                                       float bx1, float by1, float bx2, float by2, float areaB)
{
    float xx1 = fmaxf(ax1, bx1);
    float yy1 = fmaxf(ay1, by1);
    float xx2 = fminf(ax2, bx2);
    float yy2 = fminf(ay2, by2);
    float inter = fmaxf(xx2 - xx1 + 1.0f, 0.0f) * fmaxf(yy2 - yy1 + 1.0f, 0.0f);
    return inter / (areaA + areaB - inter);
}

__device__ __forceinline__ unsigned long long pack_sl(float s, int c)
{
    return ((unsigned long long)__float_as_uint(s) << 32) | (unsigned)(CC - c);
}

// shared memory: NMS arrays / select arrays, unioned across phases
struct SmemNMS {
    int   cnt;
    float cs[NN];
    int   cn[NN];
    float bx1[NN], by1[NN], bx2[NN], by2[NN], bar[NN];
    short rankOf[NN];
    int   ord[NN];
    unsigned char keep[NN];
    unsigned smask[128][4];
};
struct SmemSel {
    float vals[NN];
    float wmin[32];
};
union SmemAll { SmemNMS nms; SmemSel sel; };

// ---------------------------------------------------------------------------
// persistent kernel: softmax -> NMS -> select -> feature mask
// ---------------------------------------------------------------------------
__global__ __launch_bounds__(TPB, 1) void k_all(const float* __restrict__ logits,
                                                const float* __restrict__ reg,
                                                const float* __restrict__ props,
                                                const float4* __restrict__ feats,
                                                float* __restrict__ out)
{
    __shared__ SmemAll sm;
    const int tid  = threadIdx.x;
    const int lane = tid & 31;
    const int wid  = tid >> 5;

    // ---------------- Phase A: softmax, one warp per (b,n) row -------------
    {
        int gidx = blockIdx.x * TPB + tid;
        if (gidx < BB * NN) g_best[gidx] = 0ull;

        int gw = blockIdx.x * (TPB / 32) + wid;   // 148*32 = 4736 warps >= 1024 rows
        if (gw < BB * NN) {
            int b = gw >> 9, n = gw & 511;
            const float* lrow = logits + gw * CC;
            float x[5];
            float m = -INFINITY;
            #pragma unroll
            for (int j = 0; j < 5; j++) {
                int c = lane + 32 * j;
                x[j] = (c < CC) ? lrow[c] : -INFINITY;
                m = fmaxf(m, x[j]);
            }
            #pragma unroll
            for (int s = 16; s > 0; s >>= 1)
                m = fmaxf(m, __shfl_xor_sync(0xffffffffu, m, s));
            float e[5], sum = 0.f;
            #pragma unroll
            for (int j = 0; j < 5; j++) {
                int c = lane + 32 * j;
                e[j] = (c < CC) ? expf(x[j] - m) : 0.f;
                sum += e[j];
            }
            #pragma unroll
            for (int s = 16; s > 0; s >>= 1)
                sum += __shfl_xor_sync(0xffffffffu, sum, s);
            float inv = 1.f / sum;
            #pragma unroll
            for (int j = 0; j < 5; j++) {
                int c = lane + 32 * j;
                if (c < CC)
                    g_prob[((b * CC + c) << 9) + n] = e[j] * inv;
            }
        }
    }
    grid_sync();

    // ---------------- Phase B: per-(b,c) NMS -> atomicMax g_best -----------
    for (int task = blockIdx.x; task < BB * (CC - 1); task += GRID) {
        __syncthreads();                       // smem reuse across tasks
        int b = task / (CC - 1), c = task % (CC - 1) + 1;
        const float* prow = g_prob + ((b * CC + c) << 9);

        if (tid == 0) sm.nms.cnt = 0;
        __syncthreads();

        float s = 0.f;
        int slot = -1;
        if (tid < NN) {
            s = prow[tid];
            if (s > SCORE_THRESH) slot = atomicAdd(&sm.nms.cnt, 1);
            if (slot >= 0) { sm.nms.cs[slot] = s; sm.nms.cn[slot] = tid; }
        }
        __syncthreads();

        int M = sm.nms.cnt;
        if (M == 0) continue;

        if (M <= 128) {
            // ---- bitmask path: few barriers, no serialized greedy ----------
            if (tid < M) {
                int n = sm.nms.cn[tid];
                const float* pb = props + (b * NN + n) * 4;
                const float* rg = reg + (size_t)(((b * NN + n) * CC) + c) * 4;
                decode_clip(pb, rg, sm.nms.bx1[tid], sm.nms.by1[tid],
                            sm.nms.bx2[tid], sm.nms.by2[tid]);
                sm.nms.bar[tid] = (sm.nms.bx2[tid] - sm.nms.bx1[tid] + 1.0f)
                                * (sm.nms.by2[tid] - sm.nms.by1[tid] + 1.0f);
                // rank: descending score, ties -> ascending original index
                float ms = sm.nms.cs[tid]; int mn = sm.nms.cn[tid];
                int r = 0;
                for (int j = 0; j < M; j++) {
                    float sj = sm.nms.cs[j]; int nj = sm.nms.cn[j];
                    if ((sj > ms) || (sj == ms && nj < mn)) r++;
                }
                sm.nms.rankOf[tid] = (short)r;
                sm.nms.smask[tid][0] = 0; sm.nms.smask[tid][1] = 0;
                sm.nms.smask[tid][2] = 0; sm.nms.smask[tid][3] = 0;
            }
            __syncthreads();

            // all-pairs IoU into rank-space suppression masks
            for (int p = tid; p < M * M; p += TPB) {
                int i = p / M, j = p - i * M;
                int ri = sm.nms.rankOf[i], rj = sm.nms.rankOf[j];
                if (rj > ri) {
                    float iou = iou_f(sm.nms.bx1[i], sm.nms.by1[i], sm.nms.bx2[i],
                                      sm.nms.by2[i], sm.nms.bar[i],
                                      sm.nms.bx1[j], sm.nms.by1[j], sm.nms.bx2[j],
                                      sm.nms.by2[j], sm.nms.bar[j]);
                    if (iou > NMS_THRESH_F)
                        atomicOr(&sm.nms.smask[ri][rj >> 5], 1u << (rj & 31));
                }
            }
            __syncthreads();

            // redundant greedy resolve in registers (broadcast smem reads)
            unsigned k0, k1, k2, k3;
            k0 = (M >= 32)  ? 0xffffffffu : ((1u << M) - 1u);
            k1 = (M >= 64)  ? 0xffffffffu : (M > 32 ? ((1u << (M - 32)) - 1u) : 0u);
            k2 = (M >= 96)  ? 0xffffffffu : (M > 64 ? ((1u << (M - 64)) - 1u) : 0u);
            k3 = (M >= 128) ? 0xffffffffu : (M > 96 ? ((1u << (M - 96)) - 1u) : 0u);
            for (int r = 0; r < M; r++) {
                unsigned kw = (r < 32) ? k0 : (r < 64) ? k1 : (r < 96) ? k2 : k3;
                if ((kw >> (r & 31)) & 1u) {
                    k0 &= ~sm.nms.smask[r][0];
                    k1 &= ~sm.nms.smask[r][1];
                    k2 &= ~sm.nms.smask[r][2];
                    k3 &= ~sm.nms.smask[r][3];
                }
            }
            // M <= 128 < TOPN_PER_CLS: no per-class cap needed
            if (tid < M) {
                int r = sm.nms.rankOf[tid];
                unsigned kw = (r < 32) ? k0 : (r < 64) ? k1 : (r < 96) ? k2 : k3;
                if ((kw >> (r & 31)) & 1u)
                    atomicMax(&g_best[b * NN + sm.nms.cn[tid]],
                              pack_sl(sm.nms.cs[tid], c));
            }
            continue;
        }

        // ---- legacy path (M > 128, essentially never) ----------------------
        if (tid < M) {
            int n = sm.nms.cn[tid];
            const float* pb = props + (b * NN + n) * 4;
            const float* rg = reg + (size_t)(((b * NN + n) * CC) + c) * 4;
            decode_clip(pb, rg, sm.nms.bx1[tid], sm.nms.by1[tid],
                        sm.nms.bx2[tid], sm.nms.by2[tid]);
            sm.nms.bar[tid] = (sm.nms.bx2[tid] - sm.nms.bx1[tid] + 1.0f)
                            * (sm.nms.by2[tid] - sm.nms.by1[tid] + 1.0f);
            sm.nms.keep[tid] = 1;
            sm.nms.ord[tid] = tid;
        }
        int P = 1;
        while (P < M) P <<= 1;
        if (tid >= M && tid < P) {
            sm.nms.cs[tid] = -INFINITY; sm.nms.cn[tid] = 1 << 30; sm.nms.ord[tid] = tid;
        }
        __syncthreads();

        for (int k = 2; k <= P; k <<= 1) {
            for (int j = k >> 1; j > 0; j >>= 1) {
                if (tid < P) {
                    int ixj = tid ^ j;
                    if (ixj > tid) {
                        int a = sm.nms.ord[tid], bo = sm.nms.ord[ixj];
                        float sa = sm.nms.cs[a], sb = sm.nms.cs[bo];
                        bool pa = (sa > sb) || (sa == sb && sm.nms.cn[a] < sm.nms.cn[bo]);
                        bool desc = ((tid & k) == 0);
                        bool sw = desc ? !pa : pa;
                        if (sw) { sm.nms.ord[tid] = bo; sm.nms.ord[ixj] = a; }
                    }
                }
                __syncthreads();
            }
        }

        for (int i = 0; i < M - 1; i++) {
            __syncthreads();
            int oi = sm.nms.ord[i];
            if (!sm.nms.keep[oi]) continue;
            float ax1 = sm.nms.bx1[oi], ay1 = sm.nms.by1[oi];
            float ax2 = sm.nms.bx2[oi], ay2 = sm.nms.by2[oi], aar = sm.nms.bar[oi];
            for (int t = i + 1 + tid; t < M; t += TPB) {
                int ot = sm.nms.ord[t];
                if (!sm.nms.keep[ot]) continue;
                float iou = iou_f(ax1, ay1, ax2, ay2, aar,
                                  sm.nms.bx1[ot], sm.nms.by1[ot],
                                  sm.nms.bx2[ot], sm.nms.by2[ot], sm.nms.bar[ot]);
                if (iou > NMS_THRESH_F) sm.nms.keep[ot] = 0;
            }
        }
        __syncthreads();

        if (tid == 0) {
            int cum = 0;
            for (int t = 0; t < M; t++) {
                int ot = sm.nms.ord[t];
                if (sm.nms.keep[ot]) { if (++cum > TOPN_PER_CLS) sm.nms.keep[ot] = 0; }
            }
        }
        __syncthreads();

        if (tid < M && sm.nms.keep[tid])
            atomicMax(&g_best[b * NN + sm.nms.cn[tid]],
                      pack_sl(sm.nms.cs[tid], c));
    }
    grid_sync();

    // ---------------- Phase C: per-image select (blocks 0..BB-1) -----------
    if (blockIdx.x < BB) {
        int b = blockIdx.x;
        int n = tid;
        bool active = n < NN;

        unsigned long long pk = active ? g_best[b * NN + n] : 0ull;
        float best = __uint_as_float((unsigned)(pk >> 32));
        int   lab  = CC - (int)(pk & 0xffffffffu);
        bool  v0   = pk != 0ull;

        if (active) sm.sel.vals[n] = v0 ? best : -1.0f;
        int num = __syncthreads_count(active && v0);

        // rank = #{j : vals[j] > mine}; broadcast smem reads, no barriers
        float myv = active ? sm.sel.vals[n] : -1.0f;
        int rk = 0;
        #pragma unroll 8
        for (int j = 0; j < NN; j++)
            rk += (sm.sel.vals[j] > myv);

        // kth-largest = min{v : rank <= 99}
        float cand = (active && rk <= DET_PER_IMG - 1) ? myv : INFINITY;
        #pragma unroll
        for (int s = 16; s > 0; s >>= 1)
            cand = fminf(cand, __shfl_xor_sync(0xffffffffu, cand, s));
        if (lane == 0) sm.sel.wmin[wid] = cand;
        __syncthreads();
        if (tid < 32) {
            float c2 = sm.sel.wmin[tid];
            #pragma unroll
            for (int s = 16; s > 0; s >>= 1)
                c2 = fminf(c2, __shfl_xor_sync(0xffffffffu, c2, s));
            if (tid == 0) sm.sel.wmin[0] = c2;
        }
        __syncthreads();
        float thr = (num > DET_PER_IMG) ? sm.sel.wmin[0] : -1.0f;

        if (active) {
            bool det = v0 && (best >= thr);
            float X1 = 0.f, Y1 = 0.f, X2 = 0.f, Y2 = 0.f, sc = 0.f, lb = 0.f, dv = 0.f;
            if (det) {
                const float* pb = props + (b * NN + n) * 4;
                const float* rg = reg + (size_t)(((b * NN + n) * CC) + lab) * 4;
                decode_clip(pb, rg, X1, Y1, X2, Y2);
                sc = best; lb = (float)lab; dv = 1.f;
            }
            int idx = b * NN + n;
            out[OFF_BOXES + idx * 4 + 0] = X1;
            out[OFF_BOXES + idx * 4 + 1] = Y1;
            out[OFF_BOXES + idx * 4 + 2] = X2;
            out[OFF_BOXES + idx * 4 + 3] = Y2;
            out[OFF_SCORES + idx] = sc;
            out[OFF_LABELS + idx] = lb;
            out[OFF_VALID  + idx] = dv;
            g_validf[idx] = dv;
        }
    }
    grid_sync();

    // ---------------- Phase D: features * det_valid ------------------------
    {
        float4* fout = (float4*)(out + OFF_FEATS);
        int gtid = blockIdx.x * TPB + tid;
        const int NT = GRID * TPB;
        for (int i = gtid; i < SZ_FEATS / 4; i += NT) {
            float m = g_validf[i >> 10];   // DD/4 = 1024 float4 per row
            float4 v = feats[i];
            v.x *= m; v.y *= m; v.z *= m; v.w *= m;
            fout[i] = v;
        }
    }
}

// ---------------------------------------------------------------------------
extern "C" void kernel_launch(void* const* d_in, const int* in_sizes, int n_in,
                              void* d_out, int out_size)
{
    const float *logits = nullptr, *reg = nullptr, *props = nullptr, *feats = nullptr;
    for (int i = 0; i < n_in; i++) {
        switch (in_sizes[i]) {
            case SZ_LOGITS: logits = (const float*)d_in[i]; break;
            case SZ_REG:    reg    = (const float*)d_in[i]; break;
            case SZ_PROPS:  props  = (const float*)d_in[i]; break;
            case SZ_FEATS:  feats  = (const float*)d_in[i]; break;
            default: break;
        }
    }
    float* out = (float*)d_out;
    k_all<<<GRID, TPB>>>(logits, reg, props, (const float4*)feats, out);
    (void)out_size;
}